// round 15
// baseline (speedup 1.0000x reference)
#include <cuda_runtime.h>
#include <math.h>
#include <float.h>

// Problem constants (fixed by the reference setup_inputs)
#define BB 8
#define NN 16384
#define G 64
#define NC (G * G * G)             // 262144 = 32 * 8192
#define NCP (NC + 8)               // padded per-grid stride (16B-aligned u16 slabs)
#define NGRIDS 16                  // (batch, side): side 0 = pred, 1 = target
#define XMIN (-5.0f)
#define INV_CS 6.4f
#define CS_SAFE 0.15624f
#define BOUND1 (CS_SAFE * CS_SAFE)                  // exact after 3^3 box
#define BOUND4 (16.0f * CS_SAFE * CS_SAFE)          // exact after 9^3 box
#define BOUND8 (64.0f * CS_SAFE * CS_SAFE)          // exact after 17^3 box
#define SUBC 8192                  // cells per scan sub-block
#define NSUB 32                    // sub-blocks per grid
#define NBLK (NGRIDS * NSUB)       // 512
#define NOISE4 (BB * NN * 3 / 4)   // 98304 float4 elements

// Static device scratch (allocation-free, graph-capture safe).
// Invariant at entry of each kernel_launch: g_count==0, g_acc==0,
// g_qcount==0, g_qcount2==0, g_look==0, g_done==0.
__device__ __align__(16) int            g_count[NGRIDS * NC];
__device__ __align__(16) unsigned short g_start[NGRIDS * NCP];
__device__ float4 g_pts[NGRIDS * NN];
__device__ int    g_queue[NGRIDS * NN];
__device__ int    g_queue2[NGRIDS * NN];   // staging (cell|rank) then far-tail queue
__device__ int    g_qcount, g_qcount2, g_done;
__device__ unsigned long long g_look[NBLK];   // decoupled-lookback slots
__device__ double g_acc[2];        // [0] noise L1 sum, [1] chamfer sum

#define LOOK_AGG (1ull << 62)
#define LOOK_PRE (2ull << 62)
#define LOOK_VAL 0x3fffffffffffffffull

__device__ __forceinline__ int cell_of(float v) {
    int c = (int)floorf((v - XMIN) * INV_CS);
    return min(max(c, 0), G - 1);
}

// ---------------------------------------------------------------------------
// Fused: per-point cell counting + per-point rank staging + noise L1 sum.
// The atomicAdd's return value IS the point's rank within its cell; pack
// cell (18 bits) | rank (14 bits, max 16383) for an atomic-free scatter.
__global__ void __launch_bounds__(256) count_noise_kernel(
        const float* __restrict__ pred, const float* __restrict__ tgt,
        const float* __restrict__ pn, const float* __restrict__ an) {
    int tid = blockIdx.x * blockDim.x + threadIdx.x;  // 262144 threads

    float s = 0.0f;
    if (tid < NOISE4) {
        float4 x = ((const float4*)pn)[tid];
        float4 y = ((const float4*)an)[tid];
        s = fabsf(x.x - y.x) + fabsf(x.y - y.y) +
            fabsf(x.z - y.z) + fabsf(x.w - y.w);
    }
#pragma unroll
    for (int o = 16; o > 0; o >>= 1) s += __shfl_down_sync(0xffffffffu, s, o);
    __shared__ float ws[8];
    int lane = threadIdx.x & 31, w = threadIdx.x >> 5;
    if (lane == 0) ws[w] = s;

    int g = tid >> 14, i = tid & (NN - 1);
    int batch = g >> 1, side = g & 1;
    const float* p = (side ? tgt : pred) + (size_t)(batch * NN + i) * 3;
    int c = (cell_of(p[2]) * G + cell_of(p[1])) * G + cell_of(p[0]);
    int rank = atomicAdd(&g_count[g * NC + c], 1);
    g_queue2[tid] = c | (rank << 18);

    __syncthreads();
    if (w == 0) {
        s = (lane < 8) ? ws[lane] : 0.0f;
#pragma unroll
        for (int o = 4; o > 0; o >>= 1) s += __shfl_down_sync(0xffu, s, o);
        if (lane == 0 && s != 0.0f) atomicAdd(&g_acc[0], (double)s);
    }
}

// ---------------------------------------------------------------------------
// Single-pass exclusive scan with decoupled lookback (per-grid chains of 32
// sub-blocks; all 512 blocks co-resident -> safe). Writes uint16 prefixes
// (all values <= 16384). Re-zeroes g_count (stays zero for the next call).
__global__ void __launch_bounds__(256) scan_kernel() {
    int t = threadIdx.x, lane = t & 31, w = t >> 5;
    int g = blockIdx.x >> 5, j = blockIdx.x & 31;
    int* cnt = g_count + blockIdx.x * SUBC;
    unsigned short* st = g_start + g * NCP + j * SUBC;

    int4* c4 = (int4*)(cnt + t * 32);
    int4 v[8];
    int ts = 0;
#pragma unroll
    for (int i = 0; i < 8; i++) {
        v[i] = c4[i];
        ts += v[i].x + v[i].y + v[i].z + v[i].w;
    }
    int xs = ts;
#pragma unroll
    for (int o = 1; o < 32; o <<= 1) {
        int y = __shfl_up_sync(0xffffffffu, xs, o);
        if (lane >= o) xs += y;
    }
    __shared__ int wsum[8];
    __shared__ int s_exc;
    if (lane == 31) wsum[w] = xs;
    __syncthreads();
    int woff = 0;
#pragma unroll
    for (int k = 0; k < 8; k++) woff += (k < w) ? wsum[k] : 0;

    if (t == 0) {
        int agg = 0;
        for (int k = 0; k < 8; k++) agg += wsum[k];
        int base = blockIdx.x & ~31;
        if (j == 0) {
            atomicExch(&g_look[blockIdx.x], LOOK_PRE | (unsigned long long)agg);
            s_exc = 0;
        } else {
            atomicExch(&g_look[blockIdx.x], LOOK_AGG | (unsigned long long)agg);
            long long exc = 0;
            for (int k = j - 1; k >= 0; ) {
                unsigned long long u;
                do { u = atomicAdd(&g_look[base + k], 0ull); } while (!(u >> 62));
                exc += (long long)(u & LOOK_VAL);
                if ((u >> 62) == 2) break;
                k--;
            }
            atomicExch(&g_look[blockIdx.x],
                       LOOK_PRE | (unsigned long long)(exc + agg));
            s_exc = (int)exc;
        }
    }
    __syncthreads();

    int run = s_exc + woff + (xs - ts);
    unsigned pk[16];
#pragma unroll
    for (int i = 0; i < 8; i++) {
        unsigned s0 = (unsigned)run & 0xffffu; run += v[i].x;
        unsigned s1 = (unsigned)run & 0xffffu; run += v[i].y;
        unsigned s2 = (unsigned)run & 0xffffu; run += v[i].z;
        unsigned s3 = (unsigned)run & 0xffffu; run += v[i].w;
        pk[i * 2]     = s0 | (s1 << 16);
        pk[i * 2 + 1] = s2 | (s3 << 16);
        c4[i] = make_int4(0, 0, 0, 0);
    }
    uint4* st4 = (uint4*)(st + t * 32);
#pragma unroll
    for (int i = 0; i < 4; i++)
        st4[i] = make_uint4(pk[i * 4], pk[i * 4 + 1], pk[i * 4 + 2], pk[i * 4 + 3]);
    if (j == 31 && t == 255)
        g_start[g * NCP + NC] = (unsigned short)run;  // == NN = 16384? no: fits? 16384 <= 65535 ok
}

// ---------------------------------------------------------------------------
// Atomic-free scatter: idx = start[cell] + rank (rank staged by count).
__global__ void __launch_bounds__(256) scatter_kernel(
        const float* __restrict__ pred, const float* __restrict__ tgt) {
    int tid = blockIdx.x * blockDim.x + threadIdx.x;
    int g = tid >> 14, i = tid & (NN - 1);
    int batch = g >> 1, side = g & 1;
    const float* p = (side ? tgt : pred) + (size_t)(batch * NN + i) * 3;
    float x = p[0], y = p[1], z = p[2];
    int packed = g_queue2[tid];
    int c = packed & 0x3ffff;
    int rank = ((unsigned)packed) >> 18;
    int idx = (int)g_start[g * NCP + c] + rank;
    g_pts[g * NN + idx] = make_float4(x, y, z, 0.0f);
}

// ---------------------------------------------------------------------------
// Pass 1: uniform 3^3 box per thread; 9 x-rows scanned depth-first in
// parallel (9 independent min-chains, MLP ~9). Escalations -> g_queue.
__global__ void __launch_bounds__(256) query_kernel() {
    int tid = blockIdx.x * blockDim.x + threadIdx.x;
    int qg = tid >> 14, i = tid & (NN - 1);
    int batch = qg >> 1, side = qg & 1;
    int tg = batch * 2 + (1 - side);

    float4 p = g_pts[qg * NN + i];
    const unsigned short* st = g_start + tg * NCP;
    const float4* pts = g_pts + (size_t)tg * NN;

    int cx = cell_of(p.x), cy = cell_of(p.y), cz = cell_of(p.z);
    int x0 = max(cx - 1, 0), x1 = min(cx + 1, G - 1);

    int beg[9], len[9];
    int maxl = 0;
#pragma unroll
    for (int j = 0; j < 9; j++) {
        int z = cz + (j / 3) - 1;
        int y = cy + (j % 3) - 1;
        bool ok = ((unsigned)z < G) && ((unsigned)y < G);
        int zc = min(max(z, 0), G - 1);
        int yc = min(max(y, 0), G - 1);
        int cb = (zc * G + yc) * G;
        int b0 = st[cb + x0];
        int e0 = st[cb + x1 + 1];
        beg[j] = b0;
        len[j] = ok ? (e0 - b0) : 0;
        maxl = max(maxl, len[j]);
    }

    float bacc[9];
#pragma unroll
    for (int j = 0; j < 9; j++) bacc[j] = FLT_MAX;

    for (int k = 0; k < maxl; k++) {
#pragma unroll
        for (int j = 0; j < 9; j++) {
            if (k < len[j]) {
                float4 q = pts[beg[j] + k];
                float dx = p.x - q.x, dy = p.y - q.y, dz = p.z - q.z;
                bacc[j] = fminf(bacc[j], fmaf(dx, dx, fmaf(dy, dy, dz * dz)));
            }
        }
    }
    float b = bacc[0];
#pragma unroll
    for (int j = 1; j < 9; j++) b = fminf(b, bacc[j]);

    bool needq = (b > BOUND1);
    float contrib = needq ? 0.0f : b;

    unsigned m = __ballot_sync(0xffffffffu, needq);
    if (m) {
        int lane = threadIdx.x & 31;
        int leader = __ffs(m) - 1;
        int base = 0;
        if (lane == leader) base = atomicAdd(&g_qcount, __popc(m));
        base = __shfl_sync(0xffffffffu, base, leader);
        if (needq)
            g_queue[base + __popc(m & ((1u << lane) - 1u))] = tid;
    }

    float v = contrib;
#pragma unroll
    for (int o = 16; o > 0; o >>= 1) v += __shfl_down_sync(0xffffffffu, v, o);
    __shared__ float ws[8];
    int lane = threadIdx.x & 31, w = threadIdx.x >> 5;
    if (lane == 0) ws[w] = v;
    __syncthreads();
    if (w == 0) {
        v = (lane < 8) ? ws[lane] : 0.0f;
#pragma unroll
        for (int o = 4; o > 0; o >>= 1) v += __shfl_down_sync(0xffu, v, o);
        if (lane == 0) atomicAdd(&g_acc[1], (double)v);
    }
}

// ---------------------------------------------------------------------------
// Pass 2: warp-per-query from the flat queue, uniform 9^3 box as 81 x-rows
// over lanes. Exact if <= (4*cs)^2; else push to queue2.
__global__ void __launch_bounds__(256) resolve_kernel() {
    int lane = threadIdx.x & 31;
    int wib = threadIdx.x >> 5;
    int gwarp = blockIdx.x * 8 + wib;
    int nwarps = gridDim.x * 8;
    int qn = g_qcount;

    float wsum = 0.0f;
    for (int qi = gwarp; qi < qn; qi += nwarps) {
        int tid = g_queue[qi];
        int qg = tid >> 14, i = tid & (NN - 1);
        int batch = qg >> 1, side = qg & 1;
        int tg = batch * 2 + (1 - side);

        float4 p = g_pts[qg * NN + i];
        const unsigned short* st = g_start + tg * NCP;
        const float4* pts = g_pts + (size_t)tg * NN;
        int cx = cell_of(p.x), cy = cell_of(p.y), cz = cell_of(p.z);
        int xl = max(cx - 4, 0), xh = min(cx + 4, G - 1);

        float best = FLT_MAX;
#pragma unroll 3
        for (int row = lane; row < 81; row += 32) {
            int z = cz + row / 9 - 4;
            int y = cy + row % 9 - 4;
            if ((unsigned)z < G && (unsigned)y < G) {
                int cb = (z * G + y) * G;
                int b0 = st[cb + xl];
                int e0 = st[cb + xh + 1];
                for (int k = b0; k < e0; k++) {
                    float4 q = pts[k];
                    float ax = p.x - q.x, ay = p.y - q.y, az = p.z - q.z;
                    best = fminf(best, fmaf(ax, ax, fmaf(ay, ay, az * az)));
                }
            }
        }
#pragma unroll
        for (int o = 16; o > 0; o >>= 1)
            best = fminf(best, __shfl_xor_sync(0xffffffffu, best, o));

        if (lane == 0) {
            if (best <= BOUND4) {
                wsum += best;
            } else {
                int q2 = atomicAdd(&g_qcount2, 1);
                g_queue2[q2] = tid;
            }
        }
    }

    __shared__ float ws[8];
    if (lane == 0) ws[wib] = wsum;
    __syncthreads();
    if (threadIdx.x == 0) {
        float s = 0.0f;
        for (int j = 0; j < 8; j++) s += ws[j];
        if (s != 0.0f) atomicAdd(&g_acc[1], (double)s);
    }
}

// ---------------------------------------------------------------------------
// Far tail: block-per-query. 17^3 pre-pass, else full brute force over NN.
// Re-zeroes g_look; LAST block finalizes the output (fence + counter).
__global__ void __launch_bounds__(1024) brute_kernel(float* __restrict__ out) {
    int t = threadIdx.x, lane = t & 31, w = t >> 5;
    if (t == 0) g_look[blockIdx.x] = 0ull;  // 512 blocks == NBLK

    int qn2 = g_qcount2;
    __shared__ float ws[32];
    __shared__ float s_best;
    float bsum = 0.0f;  // accumulated by thread 0

    for (int q = blockIdx.x; q < qn2; q += gridDim.x) {
        int tid = g_queue2[q];
        int qg = tid >> 14, i = tid & (NN - 1);
        int batch = qg >> 1, side = qg & 1;
        int tg = batch * 2 + (1 - side);

        float4 p = g_pts[qg * NN + i];
        const unsigned short* st = g_start + tg * NCP;
        const float4* pts = g_pts + (size_t)tg * NN;
        int cx = cell_of(p.x), cy = cell_of(p.y), cz = cell_of(p.z);

        // 17^3 pre-pass
        float best = FLT_MAX;
        if (t < 289) {
            int z = cz + t / 17 - 8;
            int y = cy + t % 17 - 8;
            if ((unsigned)z < G && (unsigned)y < G) {
                int xl = max(cx - 8, 0), xh = min(cx + 8, G - 1);
                int cb = (z * G + y) * G;
                int b0 = st[cb + xl];
                int e0 = st[cb + xh + 1];
                for (int k = b0; k < e0; k++) {
                    float4 qq = pts[k];
                    float ax = p.x - qq.x, ay = p.y - qq.y, az = p.z - qq.z;
                    best = fminf(best, fmaf(ax, ax, fmaf(ay, ay, az * az)));
                }
            }
        }
#pragma unroll
        for (int o = 16; o > 0; o >>= 1)
            best = fminf(best, __shfl_xor_sync(0xffffffffu, best, o));
        if (lane == 0) ws[w] = best;
        __syncthreads();
        if (t == 0) {
            float bm = ws[0];
            for (int j = 1; j < 32; j++) bm = fminf(bm, ws[j]);
            s_best = bm;
        }
        __syncthreads();
        float bmin = s_best;
        __syncthreads();

        if (bmin > BOUND8) {
            best = FLT_MAX;
#pragma unroll 1
            for (int k = t; k < NN; k += 4096) {
                float4 q0 = pts[k];
                float4 q1 = pts[k + 1024];
                float4 q2 = pts[k + 2048];
                float4 q3 = pts[k + 3072];
                float dx, dy, dz, d;
                dx = p.x - q0.x; dy = p.y - q0.y; dz = p.z - q0.z;
                d = fmaf(dx, dx, fmaf(dy, dy, dz * dz)); best = fminf(best, d);
                dx = p.x - q1.x; dy = p.y - q1.y; dz = p.z - q1.z;
                d = fmaf(dx, dx, fmaf(dy, dy, dz * dz)); best = fminf(best, d);
                dx = p.x - q2.x; dy = p.y - q2.y; dz = p.z - q2.z;
                d = fmaf(dx, dx, fmaf(dy, dy, dz * dz)); best = fminf(best, d);
                dx = p.x - q3.x; dy = p.y - q3.y; dz = p.z - q3.z;
                d = fmaf(dx, dx, fmaf(dy, dy, dz * dz)); best = fminf(best, d);
            }
#pragma unroll
            for (int o = 16; o > 0; o >>= 1)
                best = fminf(best, __shfl_xor_sync(0xffffffffu, best, o));
            if (lane == 0) ws[w] = best;
            __syncthreads();
            if (t == 0) {
                float bm = ws[0];
                for (int j = 1; j < 32; j++) bm = fminf(bm, ws[j]);
                bmin = bm;
            }
        }
        if (t == 0) bsum += bmin;
        __syncthreads();
    }

    if (t == 0) {
        if (bsum != 0.0f) atomicAdd(&g_acc[1], (double)bsum);
        __threadfence();
        if (atomicAdd(&g_done, 1) == (int)gridDim.x - 1) {
            double noise   = atomicAdd(&g_acc[0], 0.0) / (double)(BB * NN * 3);
            double chamfer = atomicAdd(&g_acc[1], 0.0) / (double)(BB * NN);
            out[0] = (float)(noise + 0.1 * chamfer);
            g_acc[0] = 0.0;   // restore invariants for the next call
            g_acc[1] = 0.0;
            g_qcount = 0;
            g_qcount2 = 0;
            g_done = 0;
        }
    }
}

// ---------------------------------------------------------------------------
extern "C" void kernel_launch(void* const* d_in, const int* in_sizes, int n_in,
                              void* d_out, int out_size) {
    const float* pn = (const float*)d_in[0];
    const float* an = (const float*)d_in[1];
    const float* pp = (const float*)d_in[2];
    const float* tp = (const float*)d_in[3];
    float* out = (float*)d_out;

    count_noise_kernel<<<(NGRIDS * NN) / 256, 256>>>(pp, tp, pn, an);
    scan_kernel<<<NBLK, 256>>>();
    scatter_kernel<<<(NGRIDS * NN) / 256, 256>>>(pp, tp);
    query_kernel<<<(NGRIDS * NN) / 256, 256>>>();
    resolve_kernel<<<2048, 256>>>();
    brute_kernel<<<512, 1024>>>(out);
}

// round 16
// speedup vs baseline: 1.5251x; 1.5251x over previous
#include <cuda_runtime.h>
#include <math.h>
#include <float.h>

// Problem constants (fixed by the reference setup_inputs)
#define BB 8
#define NN 16384
#define G 64
#define NC (G * G * G)             // 262144 = 32 * 8192
#define NCP (NC + 4)               // padded per-grid stride for g_start
#define NGRIDS 16                  // (batch, side): side 0 = pred, 1 = target
#define XMIN (-5.0f)
#define INV_CS 6.4f
#define CS_SAFE 0.15624f
#define BOUND1 (CS_SAFE * CS_SAFE)                  // exact after 3^3 box
#define BOUND4 (16.0f * CS_SAFE * CS_SAFE)          // exact after 9^3 box
#define BOUND8 (64.0f * CS_SAFE * CS_SAFE)          // exact after 17^3 box
#define SUBC 8192                  // cells per scan sub-block
#define NSUB 32                    // sub-blocks per grid
#define NBLK (NGRIDS * NSUB)       // 512
#define NOISE4 (BB * NN * 3 / 4)   // 98304 float4 elements

// Static device scratch (allocation-free, graph-capture safe).
// Invariant at entry of each kernel_launch: g_count==0, g_acc==0,
// g_qcount==0, g_qcount2==0, g_look==0.
__device__ __align__(16) int    g_count[NGRIDS * NC];
__device__ __align__(16) int    g_start[NGRIDS * NCP];
__device__ float4 g_pts[NGRIDS * NN];
__device__ int    g_queue[NGRIDS * NN];
__device__ int    g_queue2[NGRIDS * NN];   // staging (cell|rank), then far-tail queue
__device__ int    g_qcount, g_qcount2;
__device__ unsigned long long g_look[NBLK];   // decoupled-lookback slots
__device__ double g_acc[2];        // [0] noise L1 sum, [1] chamfer sum

#define LOOK_AGG (1ull << 62)
#define LOOK_PRE (2ull << 62)
#define LOOK_VAL 0x3fffffffffffffffull

__device__ __forceinline__ int cell_of(float v) {
    int c = (int)floorf((v - XMIN) * INV_CS);
    return min(max(c, 0), G - 1);
}

// ---------------------------------------------------------------------------
// Fused: per-point cell counting + rank staging + noise L1 partial sum.
// The atomicAdd's return value IS the point's rank within its cell; pack
// cell (18 bits) | rank (14 bits, max 16383) for an atomic-free scatter.
__global__ void __launch_bounds__(256) count_noise_kernel(
        const float* __restrict__ pred, const float* __restrict__ tgt,
        const float* __restrict__ pn, const float* __restrict__ an) {
    int tid = blockIdx.x * blockDim.x + threadIdx.x;  // 262144 threads

    float s = 0.0f;
    if (tid < NOISE4) {
        float4 x = ((const float4*)pn)[tid];
        float4 y = ((const float4*)an)[tid];
        s = fabsf(x.x - y.x) + fabsf(x.y - y.y) +
            fabsf(x.z - y.z) + fabsf(x.w - y.w);
    }
#pragma unroll
    for (int o = 16; o > 0; o >>= 1) s += __shfl_down_sync(0xffffffffu, s, o);
    __shared__ float ws[8];
    int lane = threadIdx.x & 31, w = threadIdx.x >> 5;
    if (lane == 0) ws[w] = s;

    int g = tid >> 14, i = tid & (NN - 1);
    int batch = g >> 1, side = g & 1;
    const float* p = (side ? tgt : pred) + (size_t)(batch * NN + i) * 3;
    int c = (cell_of(p[2]) * G + cell_of(p[1])) * G + cell_of(p[0]);
    int rank = atomicAdd(&g_count[g * NC + c], 1);
    g_queue2[tid] = c | (rank << 18);

    __syncthreads();
    if (w == 0) {
        s = (lane < 8) ? ws[lane] : 0.0f;
#pragma unroll
        for (int o = 4; o > 0; o >>= 1) s += __shfl_down_sync(0xffu, s, o);
        if (lane == 0 && s != 0.0f) atomicAdd(&g_acc[0], (double)s);
    }
}

// ---------------------------------------------------------------------------
// Single-pass exclusive scan with decoupled lookback (per-grid chains of 32
// sub-blocks; all 512 blocks co-resident at 256 thr / low regs -> safe).
// Re-zeroes g_count — and since scatter is now atomic-free, it STAYS zero
// for the next call (no re-zero needed anywhere else).
__global__ void __launch_bounds__(256) scan_kernel() {
    int t = threadIdx.x, lane = t & 31, w = t >> 5;
    int g = blockIdx.x >> 5, j = blockIdx.x & 31;
    int* cnt = g_count + blockIdx.x * SUBC;
    int* st  = g_start + g * NCP + j * SUBC;

    int4* c4 = (int4*)(cnt + t * 32);
    int4 v[8];
    int ts = 0;
#pragma unroll
    for (int i = 0; i < 8; i++) {
        v[i] = c4[i];
        ts += v[i].x + v[i].y + v[i].z + v[i].w;
    }
    int xs = ts;
#pragma unroll
    for (int o = 1; o < 32; o <<= 1) {
        int y = __shfl_up_sync(0xffffffffu, xs, o);
        if (lane >= o) xs += y;
    }
    __shared__ int wsum[8];
    __shared__ int s_exc;
    if (lane == 31) wsum[w] = xs;
    __syncthreads();
    int woff = 0;
#pragma unroll
    for (int k = 0; k < 8; k++) woff += (k < w) ? wsum[k] : 0;

    if (t == 0) {
        int agg = 0;
        for (int k = 0; k < 8; k++) agg += wsum[k];
        int base = blockIdx.x & ~31;
        if (j == 0) {
            atomicExch(&g_look[blockIdx.x], LOOK_PRE | (unsigned long long)agg);
            s_exc = 0;
        } else {
            atomicExch(&g_look[blockIdx.x], LOOK_AGG | (unsigned long long)agg);
            long long exc = 0;
            for (int k = j - 1; k >= 0; ) {
                unsigned long long u;
                do { u = atomicAdd(&g_look[base + k], 0ull); } while (!(u >> 62));
                exc += (long long)(u & LOOK_VAL);
                if ((u >> 62) == 2) break;
                k--;
            }
            atomicExch(&g_look[blockIdx.x],
                       LOOK_PRE | (unsigned long long)(exc + agg));
            s_exc = (int)exc;
        }
    }
    __syncthreads();

    int run = s_exc + woff + (xs - ts);
#pragma unroll
    for (int i = 0; i < 8; i++) {
        int4 o4;
        o4.x = run; run += v[i].x;
        o4.y = run; run += v[i].y;
        o4.z = run; run += v[i].z;
        o4.w = run; run += v[i].w;
        ((int4*)(st + t * 32))[i] = o4;
        c4[i] = make_int4(0, 0, 0, 0);
    }
    if (j == 31 && t == 255) g_start[g * NCP + NC] = run;  // == NN
}

// ---------------------------------------------------------------------------
// Atomic-free scatter: idx = start[cell] + rank (rank staged by count).
__global__ void __launch_bounds__(256) scatter_kernel(
        const float* __restrict__ pred, const float* __restrict__ tgt) {
    int tid = blockIdx.x * blockDim.x + threadIdx.x;
    int g = tid >> 14, i = tid & (NN - 1);
    int batch = g >> 1, side = g & 1;
    const float* p = (side ? tgt : pred) + (size_t)(batch * NN + i) * 3;
    float x = p[0], y = p[1], z = p[2];
    int packed = g_queue2[tid];
    int c = packed & 0x3ffff;
    int rank = ((unsigned)packed) >> 18;
    int idx = g_start[g * NCP + c] + rank;
    g_pts[g * NN + idx] = make_float4(x, y, z, 0.0f);
}

// ---------------------------------------------------------------------------
// Pass 1: uniform 3^3 box per thread; 9 x-rows scanned depth-first in
// parallel (9 independent min-chains, MLP ~9). Escalations -> g_queue.
__global__ void __launch_bounds__(256) query_kernel() {
    int tid = blockIdx.x * blockDim.x + threadIdx.x;
    int qg = tid >> 14, i = tid & (NN - 1);
    int batch = qg >> 1, side = qg & 1;
    int tg = batch * 2 + (1 - side);

    float4 p = g_pts[qg * NN + i];
    const int*    st  = g_start + tg * NCP;
    const float4* pts = g_pts + (size_t)tg * NN;

    int cx = cell_of(p.x), cy = cell_of(p.y), cz = cell_of(p.z);
    int x0 = max(cx - 1, 0), x1 = min(cx + 1, G - 1);

    int beg[9], len[9];
    int maxl = 0;
#pragma unroll
    for (int j = 0; j < 9; j++) {
        int z = cz + (j / 3) - 1;
        int y = cy + (j % 3) - 1;
        bool ok = ((unsigned)z < G) && ((unsigned)y < G);
        int zc = min(max(z, 0), G - 1);
        int yc = min(max(y, 0), G - 1);
        int cb = (zc * G + yc) * G;
        int b0 = st[cb + x0];
        int e0 = st[cb + x1 + 1];
        beg[j] = b0;
        len[j] = ok ? (e0 - b0) : 0;
        maxl = max(maxl, len[j]);
    }

    float bacc[9];
#pragma unroll
    for (int j = 0; j < 9; j++) bacc[j] = FLT_MAX;

    for (int k = 0; k < maxl; k++) {
#pragma unroll
        for (int j = 0; j < 9; j++) {
            if (k < len[j]) {
                float4 q = pts[beg[j] + k];
                float dx = p.x - q.x, dy = p.y - q.y, dz = p.z - q.z;
                bacc[j] = fminf(bacc[j], fmaf(dx, dx, fmaf(dy, dy, dz * dz)));
            }
        }
    }
    float b = bacc[0];
#pragma unroll
    for (int j = 1; j < 9; j++) b = fminf(b, bacc[j]);

    bool needq = (b > BOUND1);
    float contrib = needq ? 0.0f : b;

    unsigned m = __ballot_sync(0xffffffffu, needq);
    if (m) {
        int lane = threadIdx.x & 31;
        int leader = __ffs(m) - 1;
        int base = 0;
        if (lane == leader) base = atomicAdd(&g_qcount, __popc(m));
        base = __shfl_sync(0xffffffffu, base, leader);
        if (needq)
            g_queue[base + __popc(m & ((1u << lane) - 1u))] = tid;
    }

    float v = contrib;
#pragma unroll
    for (int o = 16; o > 0; o >>= 1) v += __shfl_down_sync(0xffffffffu, v, o);
    __shared__ float ws[8];
    int lane = threadIdx.x & 31, w = threadIdx.x >> 5;
    if (lane == 0) ws[w] = v;
    __syncthreads();
    if (w == 0) {
        v = (lane < 8) ? ws[lane] : 0.0f;
#pragma unroll
        for (int o = 4; o > 0; o >>= 1) v += __shfl_down_sync(0xffu, v, o);
        if (lane == 0) atomicAdd(&g_acc[1], (double)v);
    }
}

// ---------------------------------------------------------------------------
// Pass 2: warp-per-query from the flat queue (balanced), uniform 9^3 box as
// 81 x-rows split over lanes. Exact if <= (4*cs)^2; else push to queue2.
__global__ void __launch_bounds__(256) resolve_kernel() {
    int lane = threadIdx.x & 31;
    int wib = threadIdx.x >> 5;
    int gwarp = blockIdx.x * 8 + wib;
    int nwarps = gridDim.x * 8;
    int qn = g_qcount;

    float wsum = 0.0f;
    for (int qi = gwarp; qi < qn; qi += nwarps) {
        int tid = g_queue[qi];
        int qg = tid >> 14, i = tid & (NN - 1);
        int batch = qg >> 1, side = qg & 1;
        int tg = batch * 2 + (1 - side);

        float4 p = g_pts[qg * NN + i];
        const int*    st  = g_start + tg * NCP;
        const float4* pts = g_pts + (size_t)tg * NN;
        int cx = cell_of(p.x), cy = cell_of(p.y), cz = cell_of(p.z);
        int xl = max(cx - 4, 0), xh = min(cx + 4, G - 1);

        float best = FLT_MAX;
#pragma unroll 3
        for (int row = lane; row < 81; row += 32) {
            int z = cz + row / 9 - 4;
            int y = cy + row % 9 - 4;
            if ((unsigned)z < G && (unsigned)y < G) {
                int cb = (z * G + y) * G;
                int b0 = st[cb + xl];
                int e0 = st[cb + xh + 1];
                for (int k = b0; k < e0; k++) {
                    float4 q = pts[k];
                    float ax = p.x - q.x, ay = p.y - q.y, az = p.z - q.z;
                    best = fminf(best, fmaf(ax, ax, fmaf(ay, ay, az * az)));
                }
            }
        }
#pragma unroll
        for (int o = 16; o > 0; o >>= 1)
            best = fminf(best, __shfl_xor_sync(0xffffffffu, best, o));

        if (lane == 0) {
            if (best <= BOUND4) {
                wsum += best;
            } else {
                int q2 = atomicAdd(&g_qcount2, 1);
                g_queue2[q2] = tid;
            }
        }
    }

    __shared__ float ws[8];
    if (lane == 0) ws[wib] = wsum;
    __syncthreads();
    if (threadIdx.x == 0) {
        float s = 0.0f;
        for (int j = 0; j < 8; j++) s += ws[j];
        if (s != 0.0f) atomicAdd(&g_acc[1], (double)s);
    }
}

// ---------------------------------------------------------------------------
// Far tail: block-per-query. 17^3 box pre-pass (289 rows over 1024 threads,
// exact if best <= (8*cs)^2), else full brute force over all NN points.
// Re-zeroes g_look only (g_count already clean).
__global__ void __launch_bounds__(1024) brute_kernel() {
    int t = threadIdx.x, lane = t & 31, w = t >> 5;
    if (t == 0) g_look[blockIdx.x] = 0ull;  // 512 blocks == NBLK

    int qn2 = g_qcount2;
    __shared__ float ws[32];
    __shared__ float s_best;
    float bsum = 0.0f;  // accumulated by thread 0

    for (int q = blockIdx.x; q < qn2; q += gridDim.x) {
        int tid = g_queue2[q];
        int qg = tid >> 14, i = tid & (NN - 1);
        int batch = qg >> 1, side = qg & 1;
        int tg = batch * 2 + (1 - side);

        float4 p = g_pts[qg * NN + i];
        const int*    st  = g_start + tg * NCP;
        const float4* pts = g_pts + (size_t)tg * NN;
        int cx = cell_of(p.x), cy = cell_of(p.y), cz = cell_of(p.z);

        // 17^3 pre-pass
        float best = FLT_MAX;
        if (t < 289) {
            int z = cz + t / 17 - 8;
            int y = cy + t % 17 - 8;
            if ((unsigned)z < G && (unsigned)y < G) {
                int xl = max(cx - 8, 0), xh = min(cx + 8, G - 1);
                int cb = (z * G + y) * G;
                int b0 = st[cb + xl];
                int e0 = st[cb + xh + 1];
                for (int k = b0; k < e0; k++) {
                    float4 qq = pts[k];
                    float ax = p.x - qq.x, ay = p.y - qq.y, az = p.z - qq.z;
                    best = fminf(best, fmaf(ax, ax, fmaf(ay, ay, az * az)));
                }
            }
        }
#pragma unroll
        for (int o = 16; o > 0; o >>= 1)
            best = fminf(best, __shfl_xor_sync(0xffffffffu, best, o));
        if (lane == 0) ws[w] = best;
        __syncthreads();
        if (t == 0) {
            float bm = ws[0];
            for (int j = 1; j < 32; j++) bm = fminf(bm, ws[j]);
            s_best = bm;
        }
        __syncthreads();
        float bmin = s_best;
        __syncthreads();

        if (bmin > BOUND8) {
            best = FLT_MAX;
#pragma unroll 1
            for (int k = t; k < NN; k += 4096) {
                float4 q0 = pts[k];
                float4 q1 = pts[k + 1024];
                float4 q2 = pts[k + 2048];
                float4 q3 = pts[k + 3072];
                float dx, dy, dz, d;
                dx = p.x - q0.x; dy = p.y - q0.y; dz = p.z - q0.z;
                d = fmaf(dx, dx, fmaf(dy, dy, dz * dz)); best = fminf(best, d);
                dx = p.x - q1.x; dy = p.y - q1.y; dz = p.z - q1.z;
                d = fmaf(dx, dx, fmaf(dy, dy, dz * dz)); best = fminf(best, d);
                dx = p.x - q2.x; dy = p.y - q2.y; dz = p.z - q2.z;
                d = fmaf(dx, dx, fmaf(dy, dy, dz * dz)); best = fminf(best, d);
                dx = p.x - q3.x; dy = p.y - q3.y; dz = p.z - q3.z;
                d = fmaf(dx, dx, fmaf(dy, dy, dz * dz)); best = fminf(best, d);
            }
#pragma unroll
            for (int o = 16; o > 0; o >>= 1)
                best = fminf(best, __shfl_xor_sync(0xffffffffu, best, o));
            if (lane == 0) ws[w] = best;
            __syncthreads();
            if (t == 0) {
                float bm = ws[0];
                for (int j = 1; j < 32; j++) bm = fminf(bm, ws[j]);
                bmin = bm;
            }
        }
        if (t == 0) bsum += bmin;
        __syncthreads();
    }
    if (t == 0 && bsum != 0.0f) atomicAdd(&g_acc[1], (double)bsum);
}

// ---------------------------------------------------------------------------
__global__ void finalize_kernel(float* out) {
    double noise   = g_acc[0] / (double)(BB * NN * 3);
    double chamfer = g_acc[1] / (double)(BB * NN);
    out[0] = (float)(noise + 0.1 * chamfer);
    g_acc[0] = 0.0;   // restore invariants for the next call
    g_acc[1] = 0.0;
    g_qcount = 0;
    g_qcount2 = 0;
}

// ---------------------------------------------------------------------------
extern "C" void kernel_launch(void* const* d_in, const int* in_sizes, int n_in,
                              void* d_out, int out_size) {
    const float* pn = (const float*)d_in[0];
    const float* an = (const float*)d_in[1];
    const float* pp = (const float*)d_in[2];
    const float* tp = (const float*)d_in[3];
    float* out = (float*)d_out;

    count_noise_kernel<<<(NGRIDS * NN) / 256, 256>>>(pp, tp, pn, an);
    scan_kernel<<<NBLK, 256>>>();
    scatter_kernel<<<(NGRIDS * NN) / 256, 256>>>(pp, tp);
    query_kernel<<<(NGRIDS * NN) / 256, 256>>>();
    resolve_kernel<<<2048, 256>>>();
    brute_kernel<<<512, 1024>>>();
    finalize_kernel<<<1, 1>>>(out);
}